// round 14
// baseline (speedup 1.0000x reference)
#include <cuda_runtime.h>
#include <cstdint>

#define TT 2048
#define DD 128
#define BB 8
#define BN 64

__device__ float g_q[BB*TT*DD];
__device__ float g_k[BB*TT*DD];
__device__ float g_v[BB*TT*DD];

__device__ __forceinline__ uint32_t f2tf32(float f) {
    uint32_t u; asm("cvt.rna.tf32.f32 %0, %1;" : "=r"(u) : "f"(f)); return u;
}
__device__ __forceinline__ float rtf(float f) { return __uint_as_float(f2tf32(f)); }
__device__ __forceinline__ float ex2f(float x) {
    float y; asm("ex2.approx.ftz.f32 %0, %1;" : "=f"(y) : "f"(x)); return y;
}
__device__ __forceinline__ uint32_t ldb(const float* p) { return __float_as_uint(*p); }
__device__ __forceinline__ uint32_t smem_u32(const void* p) {
    uint32_t a;
    asm("{ .reg .u64 t; cvta.to.shared.u64 t, %1; cvt.u32.u64 %0, t; }" : "=r"(a) : "l"(p));
    return a;
}

__device__ __forceinline__ void mma8(float c[4], const uint32_t a[4],
                                     uint32_t b0, uint32_t b1) {
    asm volatile("mma.sync.aligned.m16n8k8.row.col.f32.tf32.tf32.f32 "
                 "{%0,%1,%2,%3}, {%4,%5,%6,%7}, {%8,%9}, {%0,%1,%2,%3};"
                 : "+f"(c[0]), "+f"(c[1]), "+f"(c[2]), "+f"(c[3])
                 : "r"(a[0]), "r"(a[1]), "r"(a[2]), "r"(a[3]), "r"(b0), "r"(b1));
}

// scale * log2(e)
#define CS (0.08838834764831845f * 1.4426950408889634f)

// ---------------------------------------------------------------------------
// Projections via mma.sync tf32: q|k|v = x @ W. 128 rows/CTA, 8 warps (m16).
// NOTE: outputs are written rna-rounded to tf32 so the flash kernel can
// cp.async-stage K/V without a rounding pass (numerics identical to R13).
// ---------------------------------------------------------------------------
#define PXS 0
#define PWS 16896                 // 128*132
#define P_SMEM ((16896 + 17408) * 4)

__global__ __launch_bounds__(256, 1) void proj_mma(
    const float* __restrict__ x, const float* __restrict__ Wq,
    const float* __restrict__ Wk, const float* __restrict__ Wv)
{
    extern __shared__ float sm[];
    float* Xs = sm + PXS;
    float* Ws = sm + PWS;
    const int tid = threadIdx.x, wid = tid >> 5, lane = tid & 31;
    const int g = lane >> 2, t = lane & 3;
    const int row0 = blockIdx.x * 128;

    {
        const float4* src = (const float4*)(x + (size_t)row0 * DD);
        #pragma unroll
        for (int i = 0; i < 16; i++) {
            int idx = tid + 256 * i;
            int r = idx >> 5, c4 = idx & 31;
            float4 v = src[idx];
            float4 u = { rtf(v.x), rtf(v.y), rtf(v.z), rtf(v.w) };
            *(float4*)&Xs[r * 132 + c4 * 4] = u;
        }
    }
    __syncthreads();

    uint32_t xf[16][4];
    {
        const float* xb = Xs + (wid * 16) * 132;
        #pragma unroll
        for (int ks = 0; ks < 16; ks++) {
            xf[ks][0] = ldb(&xb[g * 132 + 8 * ks + t]);
            xf[ks][1] = ldb(&xb[(g + 8) * 132 + 8 * ks + t]);
            xf[ks][2] = ldb(&xb[g * 132 + 8 * ks + t + 4]);
            xf[ks][3] = ldb(&xb[(g + 8) * 132 + 8 * ks + t + 4]);
        }
    }

    const float* Wp[3] = {Wq, Wk, Wv};
    float* Gp[3] = {g_q, g_k, g_v};

    for (int o = 0; o < 3; o++) {
        __syncthreads();
        {
            const float4* src = (const float4*)Wp[o];
            #pragma unroll
            for (int i = 0; i < 16; i++) {
                int idx = tid + 256 * i;
                int r = idx >> 5, c4 = idx & 31;
                float4 v = src[idx];
                float4 u = { rtf(v.x), rtf(v.y), rtf(v.z), rtf(v.w) };
                *(float4*)&Ws[r * 136 + c4 * 4] = u;
            }
        }
        __syncthreads();

        float* grow = Gp[o] + (size_t)(row0 + wid * 16) * DD;
        #pragma unroll
        for (int nt = 0; nt < 16; nt++) {
            float c[4] = {0.f, 0.f, 0.f, 0.f};
            #pragma unroll
            for (int ks = 0; ks < 16; ks++) {
                uint32_t b0 = ldb(&Ws[(8 * ks + t) * 136 + 8 * nt + g]);
                uint32_t b1 = ldb(&Ws[(8 * ks + t + 4) * 136 + 8 * nt + g]);
                mma8(c, xf[ks], b0, b1);
            }
            // write tf32-rounded (flash consumes raw via cp.async)
            float2 v0 = {rtf(c[0]), rtf(c[1])}, v1 = {rtf(c[2]), rtf(c[3])};
            *(float2*)&grow[g * DD + 8 * nt + 2 * t]       = v0;
            *(float2*)&grow[(g + 8) * DD + 8 * nt + 2 * t] = v1;
        }
    }
}

// ---------------------------------------------------------------------------
// Flash attention (causal; flash-Q = k-proj, flash-K = q-proj).
// BM=128 rows/CTA, 8 warps (m16/warp), 1 CTA/SM, grid 128 (big-work-first).
// K/V staged with cp.async, double-buffered. Key tiles of 64.
// Kbuf[2]: [64][132], Vbuf[2]: [64][136], Ps: [128][68].
// ---------------------------------------------------------------------------
#define FK0 0
#define FK1 8448
#define FV0 16896
#define FV1 25600
#define FP  34304
#define F_SMEM ((34304 + 128 * 68) * 4)   // 172032 B

__device__ __forceinline__ void stage_async(uint32_t sbase, int buf,
                                            const float* kg, const float* vg,
                                            int tid) {
    const uint32_t koff = sbase + (buf ? FK1 : FK0) * 4;
    const uint32_t voff = sbase + (buf ? FV1 : FV0) * 4;
    const float4* ks = (const float4*)kg;
    const float4* vs = (const float4*)vg;
    #pragma unroll
    for (int i = 0; i < 8; i++) {
        int idx = tid + 256 * i;          // 0..2047 float4s
        int r = idx >> 5, c4 = idx & 31;
        uint32_t kd = koff + (uint32_t)(r * 132 + c4 * 4) * 4;
        uint32_t vd = voff + (uint32_t)(r * 136 + c4 * 4) * 4;
        asm volatile("cp.async.ca.shared.global [%0], [%1], 16;"
                     :: "r"(kd), "l"(ks + idx) : "memory");
        asm volatile("cp.async.ca.shared.global [%0], [%1], 16;"
                     :: "r"(vd), "l"(vs + idx) : "memory");
    }
}

__global__ __launch_bounds__(256, 1) void flash_mma(float* __restrict__ out)
{
    extern __shared__ float sm[];
    const uint32_t sbase = smem_u32(sm);
    float* Ps = sm + FP;

    const int tid = threadIdx.x, wid = tid >> 5, lane = tid & 31;
    const int g = lane >> 2, t = lane & 3;
    const int bid = blockIdx.x;
    const int rt = 15 - (bid >> 3);      // row-tile of 128 rows (big first)
    const int b  = bid & 7;
    const int row0 = rt * 128;

    const float* gq = g_q + (size_t)b * TT * DD;
    const float* gk = g_k + (size_t)b * TT * DD;
    const float* gv = g_v + (size_t)b * TT * DD;

    // A fragments: flash-Q rows (k-projection, already tf32-rounded)
    uint32_t qf[16][4];
    {
        const float* qb = gk + (size_t)(row0 + wid * 16) * DD;
        #pragma unroll
        for (int ks = 0; ks < 16; ks++) {
            qf[ks][0] = ldb(&qb[g * DD + 8 * ks + t]);
            qf[ks][1] = ldb(&qb[(g + 8) * DD + 8 * ks + t]);
            qf[ks][2] = ldb(&qb[g * DD + 8 * ks + t + 4]);
            qf[ks][3] = ldb(&qb[(g + 8) * DD + 8 * ks + t + 4]);
        }
    }

    float of[16][4];
    #pragma unroll
    for (int i = 0; i < 16; i++)
        #pragma unroll
        for (int j = 0; j < 4; j++) of[i][j] = 0.f;
    float mA = -1e30f, mB = -1e30f, lA = 0.f, lB = 0.f;

    const int rAl = wid * 16 + g;        // local rows owned by this thread
    const int rBl = rAl + 8;
    const int wrow_max = row0 + wid * 16 + 15;   // last global row of warp

    const int ntiles = 2 * rt + 2;       // keys 0 .. 128*(rt+1)-1
    stage_async(sbase, 0, gq, gv, tid);
    asm volatile("cp.async.commit_group;" ::: "memory");
    int cur = 0;

    for (int jt = 0; jt < ntiles; jt++) {
        __syncthreads();                 // prev iter's reads of buf[cur^1] done
        if (jt + 1 < ntiles) {
            stage_async(sbase, cur ^ 1,
                        gq + (size_t)(jt + 1) * BN * DD,
                        gv + (size_t)(jt + 1) * BN * DD, tid);
            asm volatile("cp.async.commit_group;" ::: "memory");
            asm volatile("cp.async.wait_group 1;" ::: "memory");
        } else {
            asm volatile("cp.async.wait_group 0;" ::: "memory");
        }
        __syncthreads();                 // buf[cur] visible to all warps

        if (BN * jt <= wrow_max) {       // warp has >=1 unmasked row this tile
            const float* Ks = sm + (cur ? FK1 : FK0);
            const float* Vs = sm + (cur ? FV1 : FV0);

            // ---- S = Q . K^T ----
            float sf[8][4];
            #pragma unroll
            for (int nt = 0; nt < 8; nt++) {
                float c[4] = {0.f, 0.f, 0.f, 0.f};
                #pragma unroll
                for (int ks = 0; ks < 16; ks++) {
                    uint32_t b0 = ldb(&Ks[(8 * nt + g) * 132 + 8 * ks + t]);
                    uint32_t b1 = ldb(&Ks[(8 * nt + g) * 132 + 8 * ks + t + 4]);
                    mma8(c, qf[ks], b0, b1);
                }
                sf[nt][0] = c[0]; sf[nt][1] = c[1];
                sf[nt][2] = c[2]; sf[nt][3] = c[3];
            }

            // ---- causal mask (diagonal region) ----
            if (BN * jt + BN - 1 > row0 + wid * 16) {
                int limA = row0 + rAl - BN * jt;   // max allowed col, row A
                int limB = limA + 8;               // row B
                #pragma unroll
                for (int nt = 0; nt < 8; nt++) {
                    int c0 = 8 * nt + 2 * t, c1 = c0 + 1;
                    if (c0 > limA) sf[nt][0] = -1e30f;
                    if (c1 > limA) sf[nt][1] = -1e30f;
                    if (c0 > limB) sf[nt][2] = -1e30f;
                    if (c1 > limB) sf[nt][3] = -1e30f;
                }
            }

            // ---- online softmax ----
            float mxA = -1e30f, mxB = -1e30f;
            #pragma unroll
            for (int nt = 0; nt < 8; nt++) {
                mxA = fmaxf(mxA, fmaxf(sf[nt][0], sf[nt][1]));
                mxB = fmaxf(mxB, fmaxf(sf[nt][2], sf[nt][3]));
            }
            mxA = fmaxf(mxA, __shfl_xor_sync(0xffffffffu, mxA, 1));
            mxA = fmaxf(mxA, __shfl_xor_sync(0xffffffffu, mxA, 2));
            mxB = fmaxf(mxB, __shfl_xor_sync(0xffffffffu, mxB, 1));
            mxB = fmaxf(mxB, __shfl_xor_sync(0xffffffffu, mxB, 2));
            float nmA = fmaxf(mA, mxA), nmB = fmaxf(mB, mxB);
            float aA = ex2f((mA - nmA) * CS), aB = ex2f((mB - nmB) * CS);
            mA = nmA; mB = nmB;

            float sA = 0.f, sB = 0.f;
            #pragma unroll
            for (int nt = 0; nt < 8; nt++) {
                float p0 = ex2f((sf[nt][0] - nmA) * CS);
                float p1 = ex2f((sf[nt][1] - nmA) * CS);
                float p2 = ex2f((sf[nt][2] - nmB) * CS);
                float p3 = ex2f((sf[nt][3] - nmB) * CS);
                sA += p0 + p1; sB += p2 + p3;
                float2 vA = { __uint_as_float(f2tf32(p0)), __uint_as_float(f2tf32(p1)) };
                float2 vB = { __uint_as_float(f2tf32(p2)), __uint_as_float(f2tf32(p3)) };
                *(float2*)&Ps[rAl * 68 + 8 * nt + 2 * t] = vA;
                *(float2*)&Ps[rBl * 68 + 8 * nt + 2 * t] = vB;
            }
            sA += __shfl_xor_sync(0xffffffffu, sA, 1);
            sA += __shfl_xor_sync(0xffffffffu, sA, 2);
            sB += __shfl_xor_sync(0xffffffffu, sB, 1);
            sB += __shfl_xor_sync(0xffffffffu, sB, 2);
            lA = lA * aA + sA;
            lB = lB * aB + sB;
            #pragma unroll
            for (int nt = 0; nt < 16; nt++) {
                of[nt][0] *= aA; of[nt][1] *= aA;
                of[nt][2] *= aB; of[nt][3] *= aB;
            }
            __syncwarp();   // P visible warp-wide (frags read own warp's rows)

            // ---- O += P . V ----
            uint32_t pf[8][4];
            #pragma unroll
            for (int ks = 0; ks < 8; ks++) {
                pf[ks][0] = ldb(&Ps[rAl * 68 + 8 * ks + t]);
                pf[ks][1] = ldb(&Ps[rBl * 68 + 8 * ks + t]);
                pf[ks][2] = ldb(&Ps[rAl * 68 + 8 * ks + t + 4]);
                pf[ks][3] = ldb(&Ps[rBl * 68 + 8 * ks + t + 4]);
            }
            #pragma unroll
            for (int nt = 0; nt < 16; nt++) {
                #pragma unroll
                for (int ks = 0; ks < 8; ks++) {
                    uint32_t b0 = ldb(&Vs[(8 * ks + t) * 136 + 8 * nt + g]);
                    uint32_t b1 = ldb(&Vs[(8 * ks + t + 4) * 136 + 8 * nt + g]);
                    mma8(of[nt], pf[ks], b0, b1);
                }
            }
        }
        cur ^= 1;
    }

    // ---- normalize + write ----
    float iA = 1.f / lA, iB = 1.f / lB;
    float* orow = out + ((size_t)b * TT + row0 + wid * 16) * DD;
    #pragma unroll
    for (int nt = 0; nt < 16; nt++) {
        float2 v0 = { of[nt][0] * iA, of[nt][1] * iA };
        float2 v1 = { of[nt][2] * iB, of[nt][3] * iB };
        *(float2*)&orow[g * DD + 8 * nt + 2 * t]       = v0;
        *(float2*)&orow[(g + 8) * DD + 8 * nt + 2 * t] = v1;
    }
}

extern "C" void kernel_launch(void* const* d_in, const int* in_sizes, int n_in,
                              void* d_out, int out_size)
{
    const float* x  = (const float*)d_in[0];
    const float* Wq = (const float*)d_in[1];
    const float* Wk = (const float*)d_in[2];
    const float* Wv = (const float*)d_in[3];
    float* out = (float*)d_out;

    cudaFuncSetAttribute(proj_mma, cudaFuncAttributeMaxDynamicSharedMemorySize, P_SMEM);
    cudaFuncSetAttribute(flash_mma, cudaFuncAttributeMaxDynamicSharedMemorySize, F_SMEM);

    proj_mma<<<BB * TT / 128, 256, P_SMEM>>>(x, Wq, Wk, Wv);
    flash_mma<<<128, 256, F_SMEM>>>(out);
}